// round 10
// baseline (speedup 1.0000x reference)
#include <cuda_runtime.h>

// Problem constants
#define S    256   // n_symm = 16 x 16 torus
#define NI   32    // in_features
#define NF   64    // features
#define NB   16    // batch

// Base twiddles: CW16[j] = cos(2*pi*j/16), SW16[j] = sin(2*pi*j/16)
__constant__ float CW16[16] = {
    1.0f,  0.9238795325112867f,  0.7071067811865476f,  0.3826834323650898f,
    0.0f, -0.3826834323650898f, -0.7071067811865476f, -0.9238795325112867f,
   -1.0f, -0.9238795325112867f, -0.7071067811865476f, -0.3826834323650898f,
    0.0f,  0.3826834323650898f,  0.7071067811865476f,  0.9238795325112867f
};
__constant__ float SW16[16] = {
    0.0f,  0.3826834323650898f,  0.7071067811865476f,  0.9238795325112867f,
    1.0f,  0.9238795325112867f,  0.7071067811865476f,  0.3826834323650898f,
    0.0f, -0.3826834323650898f, -0.7071067811865476f, -0.9238795325112867f,
   -1.0f, -0.9238795325112867f, -0.7071067811865476f, -0.3826834323650898f
};

// Spectra scratch — device globals, referenced ONLY from device code.
__device__ __align__(16) float2 g_xhat[S * NB * NI];   // [omega][b*32+i]
__device__ __align__(16) float2 g_khat[S * NF * NI];   // [omega][f*32+i]
__device__ __align__(16) float2 g_ohat[S * NB * NF];   // [omega][b*64+f]

// conj omega index: (u,w) -> ((16-u)%16, (16-w)%16)
__device__ __forceinline__ int conj_om(int om) {
    int u = om >> 4, w = om & 15;
    return (((16 - u) & 15) << 4) | ((16 - w) & 15);
}

// ---------------------------------------------------------------------------
// Forward 2D FFT (16x16) with 2-for-1 real packing: two real tiles become
// one complex tile z = x_t0 + i*x_t1; one complex FFT; Hermitian unpack at
// store. Grid 1280 keeps the chip full; ~2/3 the instructions of round 8.
// ---------------------------------------------------------------------------
__global__ __launch_bounds__(256)
void fft_fwd_all(const float* __restrict__ x, const float* __restrict__ kern)
{
    const int pb = blockIdx.x;
    const float* in; float2* outh; int ostride, t0;
    if (pb < (NB * NI) / 2) {
        in = x;    outh = g_xhat; ostride = NB * NI; t0 = pb * 2;
    } else {
        in = kern; outh = g_khat; ostride = NF * NI;
        t0 = (pb - (NB * NI) / 2) * 2;
    }

    __shared__ float  sr[512];             // tile0 (re), tile1 (im)
    __shared__ float2 sBt[16];
    __shared__ float2 st[16 * 17];         // pass-1 result
    __shared__ float2 zz[256];             // pass-2 result (for unpack)

    const int tid = threadIdx.x;
    const int u   = tid >> 4;
    const int w   = tid & 15;

    if (tid < 16) sBt[tid] = make_float2(CW16[tid], SW16[tid]);
    ((float2*)sr)[tid] = ((const float2*)(in + t0 * 256))[tid];
    __syncthreads();

    // forward twiddles: t_k = (c, -s); j = (-i)^k
    const float2 j1w = sBt[(4 * w) & 15];
    const float2 t1w = sBt[w], t2w = sBt[(2 * w) & 15], t3w = sBt[(3 * w) & 15];
    const float  ew  = 1.f - 2.f * (float)(w & 1);
    const float  jrw = j1w.x, jiw = -j1w.y;

    const float2 j1u = sBt[(4 * u) & 15];
    const float2 t1u = sBt[u], t2u = sBt[(2 * u) & 15], t3u = sBt[(3 * u) & 15];
    const float  eu  = 1.f - 2.f * (float)(u & 1);
    const float  jru = j1u.x, jiu = -j1u.y;

    // pass 1 (complex input z[v] = (tile0[u][v], tile1[u][v]))
    {
        float zr[16], zi[16];
        const float4* r4 = (const float4*)(sr + u * 16);
        const float4* i4 = (const float4*)(sr + 256 + u * 16);
        #pragma unroll
        for (int q = 0; q < 4; q++) {
            float4 a = r4[q], b = i4[q];
            zr[q*4+0]=a.x; zr[q*4+1]=a.y; zr[q*4+2]=a.z; zr[q*4+3]=a.w;
            zi[q*4+0]=b.x; zi[q*4+1]=b.y; zi[q*4+2]=b.z; zi[q*4+3]=b.w;
        }
        float Sx[4], Sy[4];
        #pragma unroll
        for (int r = 0; r < 4; r++) {
            float Px = fmaf(ew, zr[r + 8],  zr[r]);
            float Py = fmaf(ew, zi[r + 8],  zi[r]);
            float Qx = fmaf(ew, zr[r + 12], zr[r + 4]);
            float Qy = fmaf(ew, zi[r + 12], zi[r + 4]);
            Sx[r] = fmaf(jrw, Qx, fmaf(-jiw, Qy, Px));
            Sy[r] = fmaf(jrw, Qy, fmaf( jiw, Qx, Py));
        }
        float ar = Sx[0], ai = Sy[0];
        ar = fmaf(t1w.x, Sx[1], fmaf( t1w.y, Sy[1], ar));
        ai = fmaf(t1w.x, Sy[1], fmaf(-t1w.y, Sx[1], ai));
        ar = fmaf(t2w.x, Sx[2], fmaf( t2w.y, Sy[2], ar));
        ai = fmaf(t2w.x, Sy[2], fmaf(-t2w.y, Sx[2], ai));
        ar = fmaf(t3w.x, Sx[3], fmaf( t3w.y, Sy[3], ar));
        ai = fmaf(t3w.x, Sy[3], fmaf(-t3w.y, Sx[3], ai));
        st[u * 17 + w] = make_float2(ar, ai);
    }
    __syncthreads();

    // pass 2 (complex)
    {
        float Sx[4], Sy[4];
        #pragma unroll
        for (int r = 0; r < 4; r++) {
            float2 z0 = st[(r     ) * 17 + w];
            float2 z1 = st[(r +  4) * 17 + w];
            float2 z2 = st[(r +  8) * 17 + w];
            float2 z3 = st[(r + 12) * 17 + w];
            float Px = fmaf(eu, z2.x, z0.x), Py = fmaf(eu, z2.y, z0.y);
            float Qx = fmaf(eu, z3.x, z1.x), Qy = fmaf(eu, z3.y, z1.y);
            Sx[r] = fmaf(jru, Qx, fmaf(-jiu, Qy, Px));
            Sy[r] = fmaf(jru, Qy, fmaf( jiu, Qx, Py));
        }
        float br = Sx[0], bi = Sy[0];
        br = fmaf(t1u.x, Sx[1], fmaf( t1u.y, Sy[1], br));
        bi = fmaf(t1u.x, Sy[1], fmaf(-t1u.y, Sx[1], bi));
        br = fmaf(t2u.x, Sx[2], fmaf( t2u.y, Sy[2], br));
        bi = fmaf(t2u.x, Sy[2], fmaf(-t2u.y, Sx[2], bi));
        br = fmaf(t3u.x, Sx[3], fmaf( t3u.y, Sy[3], br));
        bi = fmaf(t3u.x, Sy[3], fmaf(-t3u.y, Sx[3], bi));
        zz[tid] = make_float2(br, bi);
    }
    __syncthreads();

    // Hermitian unpack: X1 = (Z(w)+conj Z(-w))/2, X2 = -i(Z(w)-conj Z(-w))/2
    const int co = conj_om(tid);
    if (tid <= co) {
        float2 A = zz[tid], B = zz[co];
        float x1r = 0.5f * (A.x + B.x);
        float x1i = 0.5f * (A.y - B.y);
        float x2r = 0.5f * (A.y + B.y);
        float x2i = 0.5f * (B.x - A.x);
        *reinterpret_cast<float4*>(outh + (size_t)tid * ostride + t0) =
            make_float4(x1r, x1i, x2r, x2i);
    }
}

// ---------------------------------------------------------------------------
// Per-frequency contraction on canonical omegas only; writes ohat(om) and
// conjugate partner. Non-canonical blocks exit immediately.
// ---------------------------------------------------------------------------
__global__ __launch_bounds__(256)
void contract_kernel()
{
    const int om = blockIdx.x;
    const int co = conj_om(om);
    if (om > co) return;

    const int tid = threadIdx.x;

    __shared__ float2 xh[NB * NI];        // [b][i]
    __shared__ float2 kh[NI * 65];        // [i][f] padded

    #pragma unroll
    for (int p = 0; p < 2; p++)
        xh[p * 256 + tid] = g_xhat[om * (NB * NI) + p * 256 + tid];
    #pragma unroll
    for (int p = 0; p < 8; p++) {
        int g = p * 256 + tid;
        int f = g >> 5, i = g & 31;
        kh[i * 65 + f] = g_khat[om * (NF * NI) + g];
    }
    __syncthreads();

    const int f  = tid & 63;
    const int b0 = tid >> 6;            // 0..3

    float accr[4] = {0.f, 0.f, 0.f, 0.f};
    float acci[4] = {0.f, 0.f, 0.f, 0.f};

    #pragma unroll 8
    for (int i = 0; i < NI; i++) {
        float2 kv = kh[i * 65 + f];
        #pragma unroll
        for (int r = 0; r < 4; r++) {
            float2 xv = xh[(r * 4 + b0) * NI + i];
            accr[r] = fmaf(xv.x, kv.x, fmaf(-xv.y, kv.y, accr[r]));
            acci[r] = fmaf(xv.x, kv.y, fmaf( xv.y, kv.x, acci[r]));
        }
    }

    #pragma unroll
    for (int r = 0; r < 4; r++) {
        int b = r * 4 + b0;
        g_ohat[om * (NB * NF) + b * NF + f] = make_float2(accr[r], acci[r]);
        if (om != co)
            g_ohat[co * (NB * NF) + b * NF + f] = make_float2(accr[r], -acci[r]);
    }
}

// ---------------------------------------------------------------------------
// Inverse 2D FFT + bias, 2-for-1 packed: W = ohat_f0 + i*ohat_f1 has
// IFFT(W) = out_f0 + i*out_f1 (both IFFTs are real). One complex inverse
// transform yields two output features. Inverse twiddles (c, +s).
// ---------------------------------------------------------------------------
__global__ __launch_bounds__(256)
void ifft_kernel(float* __restrict__ out, const float* __restrict__ bias)
{
    const int blk = blockIdx.x;          // 0..511
    const int b   = blk >> 5;
    const int f0  = (blk & 31) * 2;

    __shared__ float2 sBt[16];
    __shared__ float2 sin_[256];         // packed W at [omega_u*16 + omega_v]
    __shared__ float2 st[16 * 17];

    const int tid = threadIdx.x;
    const int u   = tid >> 4;
    const int w   = tid & 15;

    if (tid < 16) sBt[tid] = make_float2(CW16[tid], SW16[tid]);
    {
        float4 z = *reinterpret_cast<const float4*>(
            g_ohat + (size_t)tid * (NB * NF) + b * NF + f0);
        // W = o0 + i*o1
        sin_[tid] = make_float2(z.x - z.w, z.y + z.z);
    }
    __syncthreads();

    const float2 j1w = sBt[(4 * w) & 15];
    const float2 t1w = sBt[w], t2w = sBt[(2 * w) & 15], t3w = sBt[(3 * w) & 15];
    const float  ew  = 1.f - 2.f * (float)(w & 1);
    const float  jrw = j1w.x, jiw = j1w.y;

    const float2 j1u = sBt[(4 * u) & 15];
    const float2 t1u = sBt[u], t2u = sBt[(2 * u) & 15], t3u = sBt[(3 * u) & 15];
    const float  eu  = 1.f - 2.f * (float)(u & 1);
    const float  jru = j1u.x, jiu = j1u.y;

    // pass 1 over omega_v
    {
        float Sx[4], Sy[4];
        #pragma unroll
        for (int r = 0; r < 4; r++) {
            float2 z0 = sin_[u * 16 + r];
            float2 z1 = sin_[u * 16 + r + 4];
            float2 z2 = sin_[u * 16 + r + 8];
            float2 z3 = sin_[u * 16 + r + 12];
            float Px = fmaf(ew, z2.x, z0.x), Py = fmaf(ew, z2.y, z0.y);
            float Qx = fmaf(ew, z3.x, z1.x), Qy = fmaf(ew, z3.y, z1.y);
            Sx[r] = fmaf(jrw, Qx, fmaf(-jiw, Qy, Px));
            Sy[r] = fmaf(jrw, Qy, fmaf( jiw, Qx, Py));
        }
        // t'=(c,s): Re+=c*Sx-s*Sy, Im+=c*Sy+s*Sx
        float ar = Sx[0], ai = Sy[0];
        ar = fmaf(t1w.x, Sx[1], fmaf(-t1w.y, Sy[1], ar));
        ai = fmaf(t1w.x, Sy[1], fmaf( t1w.y, Sx[1], ai));
        ar = fmaf(t2w.x, Sx[2], fmaf(-t2w.y, Sy[2], ar));
        ai = fmaf(t2w.x, Sy[2], fmaf( t2w.y, Sx[2], ai));
        ar = fmaf(t3w.x, Sx[3], fmaf(-t3w.y, Sy[3], ar));
        ai = fmaf(t3w.x, Sy[3], fmaf( t3w.y, Sx[3], ai));
        st[u * 17 + w] = make_float2(ar, ai);
    }
    __syncthreads();

    // pass 2 over omega_u: full complex; Re -> f0, Im -> f0+1
    {
        float Sx[4], Sy[4];
        #pragma unroll
        for (int r = 0; r < 4; r++) {
            float2 z0 = st[(r     ) * 17 + w];
            float2 z1 = st[(r +  4) * 17 + w];
            float2 z2 = st[(r +  8) * 17 + w];
            float2 z3 = st[(r + 12) * 17 + w];
            float Px = fmaf(eu, z2.x, z0.x), Py = fmaf(eu, z2.y, z0.y);
            float Qx = fmaf(eu, z3.x, z1.x), Qy = fmaf(eu, z3.y, z1.y);
            Sx[r] = fmaf(jru, Qx, fmaf(-jiu, Qy, Px));
            Sy[r] = fmaf(jru, Qy, fmaf( jiu, Qx, Py));
        }
        float br = Sx[0], bi = Sy[0];
        br = fmaf(t1u.x, Sx[1], fmaf(-t1u.y, Sy[1], br));
        bi = fmaf(t1u.x, Sy[1], fmaf( t1u.y, Sx[1], bi));
        br = fmaf(t2u.x, Sx[2], fmaf(-t2u.y, Sy[2], br));
        bi = fmaf(t2u.x, Sy[2], fmaf( t2u.y, Sx[2], bi));
        br = fmaf(t3u.x, Sx[3], fmaf(-t3u.y, Sy[3], br));
        bi = fmaf(t3u.x, Sy[3], fmaf( t3u.y, Sx[3], bi));

        float* o = out + b * (NF * S) + f0 * S + tid;
        o[0] = br * (1.0f / 256.0f) + bias[f0];
        o[S] = bi * (1.0f / 256.0f) + bias[f0 + 1];
    }
}

// ---------------------------------------------------------------------------
extern "C" void kernel_launch(void* const* d_in, const int* in_sizes, int n_in,
                              void* d_out, int out_size) {
    const float* x    = (const float*)d_in[0];   // (16, 32, 256)
    const float* kern = (const float*)d_in[1];   // (64, 32, 256)
    const float* bias = (const float*)d_in[2];   // (64,)
    // d_in[3] = product_table of the 2D translation group (deterministic);
    // exploited analytically via the convolution theorem.
    float* out = (float*)d_out;                  // (16, 64, 256)

    fft_fwd_all<<<(NB * NI + NF * NI) / 2, 256>>>(x, kern);
    contract_kernel<<<S, 256>>>();
    ifft_kernel<<<(NB * NF) / 2, 256>>>(out, bias);
}

// round 11
// speedup vs baseline: 1.0094x; 1.0094x over previous
#include <cuda_runtime.h>

// Problem constants
#define S    256   // n_symm = 16 x 16 torus
#define NI   32    // in_features
#define NF   64    // features
#define NB   16    // batch
#define GRID 640   // fused kernel grid; co-resident by construction (see below)

// Base twiddles: CW16[j] = cos(2*pi*j/16), SW16[j] = sin(2*pi*j/16)
__constant__ float CW16[16] = {
    1.0f,  0.9238795325112867f,  0.7071067811865476f,  0.3826834323650898f,
    0.0f, -0.3826834323650898f, -0.7071067811865476f, -0.9238795325112867f,
   -1.0f, -0.9238795325112867f, -0.7071067811865476f, -0.3826834323650898f,
    0.0f,  0.3826834323650898f,  0.7071067811865476f,  0.9238795325112867f
};
__constant__ float SW16[16] = {
    0.0f,  0.3826834323650898f,  0.7071067811865476f,  0.9238795325112867f,
    1.0f,  0.9238795325112867f,  0.7071067811865476f,  0.3826834323650898f,
    0.0f, -0.3826834323650898f, -0.7071067811865476f, -0.9238795325112867f,
   -1.0f, -0.9238795325112867f, -0.7071067811865476f, -0.3826834323650898f
};

// Spectra scratch + barrier counter — device globals (no allocations).
__device__ __align__(16) float2 g_xhat[S * NB * NI];   // [omega][b*32+i]
__device__ __align__(16) float2 g_khat[S * NF * NI];   // [omega][f*32+i]
__device__ __align__(16) float2 g_ohat[S * NB * NF];   // [omega][b*64+f]
__device__ unsigned g_count = 0;   // monotonic generation barrier counter

// conj omega index: (u,w) -> ((16-u)%16, (16-w)%16)
__device__ __forceinline__ int conj_om(int om) {
    int u = om >> 4, w = om & 15;
    return (((16 - u) & 15) << 4) | ((16 - w) & 15);
}

// Grid-wide generation barrier. Safe because all GRID blocks are co-resident
// (launch_bounds(256,5): 5 blocks/SM x 148 SMs = 740 >= 640). Counter is
// monotonic across launches -> graph replay safe.
__device__ __forceinline__ void grid_sync() {
    __syncthreads();
    if (threadIdx.x == 0) {
        __threadfence();
        unsigned old = atomicAdd(&g_count, 1u);
        unsigned target = old - (old % GRID) + GRID;   // end of this generation
        while (atomicAdd(&g_count, 0u) < target) __nanosleep(64);
        __threadfence();
    }
    __syncthreads();
}

// ---------------------------------------------------------------------------
// Fused kernel: fft(x & kernel, 2-for-1 real packed) -> contract -> ifft,
// separated by device-side grid barriers. Removes 2 kernel-launch gaps.
// SMEM is a 20.7KB union re-laid per phase.
// ---------------------------------------------------------------------------
__global__ __launch_bounds__(256, 5)
void fused_kernel(const float* __restrict__ x, const float* __restrict__ kern,
                  const float* __restrict__ bias, float* __restrict__ out)
{
    __shared__ __align__(16) unsigned char smraw[20736];

    const int tid = threadIdx.x;
    const int u   = tid >> 4;
    const int w   = tid & 15;

    // ======================= Phase 1: forward FFTs =========================
    {
        float*  sr  = (float*) smraw;                 // 2048 B (2 tiles)
        float2* sBt = (float2*)(smraw + 2048);        //  128 B
        float2* st  = (float2*)(smraw + 2176);        // 2176 B (16*17)
        float2* zz  = (float2*)(smraw + 4352);        // 2048 B

        if (tid < 16) sBt[tid] = make_float2(CW16[tid], SW16[tid]);

        for (int pair = blockIdx.x; pair < (NB * NI + NF * NI) / 2; pair += GRID) {
            const float* in; float2* outh; int ostride, t0;
            if (pair < (NB * NI) / 2) {
                in = x;    outh = g_xhat; ostride = NB * NI; t0 = pair * 2;
            } else {
                in = kern; outh = g_khat; ostride = NF * NI;
                t0 = (pair - (NB * NI) / 2) * 2;
            }

            ((float2*)sr)[tid] = ((const float2*)(in + t0 * 256))[tid];
            __syncthreads();

            // forward twiddles: t_k = (c, -s); j = (-i)^k
            const float2 j1w = sBt[(4 * w) & 15];
            const float2 t1w = sBt[w], t2w = sBt[(2 * w) & 15], t3w = sBt[(3 * w) & 15];
            const float  ew  = 1.f - 2.f * (float)(w & 1);
            const float  jrw = j1w.x, jiw = -j1w.y;

            const float2 j1u = sBt[(4 * u) & 15];
            const float2 t1u = sBt[u], t2u = sBt[(2 * u) & 15], t3u = sBt[(3 * u) & 15];
            const float  eu  = 1.f - 2.f * (float)(u & 1);
            const float  jru = j1u.x, jiu = -j1u.y;

            // pass 1: z[v] = (tile0[u][v], tile1[u][v])
            {
                float zr[16], zi[16];
                const float4* r4 = (const float4*)(sr + u * 16);
                const float4* i4 = (const float4*)(sr + 256 + u * 16);
                #pragma unroll
                for (int q = 0; q < 4; q++) {
                    float4 a = r4[q], b = i4[q];
                    zr[q*4+0]=a.x; zr[q*4+1]=a.y; zr[q*4+2]=a.z; zr[q*4+3]=a.w;
                    zi[q*4+0]=b.x; zi[q*4+1]=b.y; zi[q*4+2]=b.z; zi[q*4+3]=b.w;
                }
                float Sx[4], Sy[4];
                #pragma unroll
                for (int r = 0; r < 4; r++) {
                    float Px = fmaf(ew, zr[r + 8],  zr[r]);
                    float Py = fmaf(ew, zi[r + 8],  zi[r]);
                    float Qx = fmaf(ew, zr[r + 12], zr[r + 4]);
                    float Qy = fmaf(ew, zi[r + 12], zi[r + 4]);
                    Sx[r] = fmaf(jrw, Qx, fmaf(-jiw, Qy, Px));
                    Sy[r] = fmaf(jrw, Qy, fmaf( jiw, Qx, Py));
                }
                float ar = Sx[0], ai = Sy[0];
                ar = fmaf(t1w.x, Sx[1], fmaf( t1w.y, Sy[1], ar));
                ai = fmaf(t1w.x, Sy[1], fmaf(-t1w.y, Sx[1], ai));
                ar = fmaf(t2w.x, Sx[2], fmaf( t2w.y, Sy[2], ar));
                ai = fmaf(t2w.x, Sy[2], fmaf(-t2w.y, Sx[2], ai));
                ar = fmaf(t3w.x, Sx[3], fmaf( t3w.y, Sy[3], ar));
                ai = fmaf(t3w.x, Sy[3], fmaf(-t3w.y, Sx[3], ai));
                st[u * 17 + w] = make_float2(ar, ai);
            }
            __syncthreads();

            // pass 2
            {
                float Sx[4], Sy[4];
                #pragma unroll
                for (int r = 0; r < 4; r++) {
                    float2 z0 = st[(r     ) * 17 + w];
                    float2 z1 = st[(r +  4) * 17 + w];
                    float2 z2 = st[(r +  8) * 17 + w];
                    float2 z3 = st[(r + 12) * 17 + w];
                    float Px = fmaf(eu, z2.x, z0.x), Py = fmaf(eu, z2.y, z0.y);
                    float Qx = fmaf(eu, z3.x, z1.x), Qy = fmaf(eu, z3.y, z1.y);
                    Sx[r] = fmaf(jru, Qx, fmaf(-jiu, Qy, Px));
                    Sy[r] = fmaf(jru, Qy, fmaf( jiu, Qx, Py));
                }
                float br = Sx[0], bi = Sy[0];
                br = fmaf(t1u.x, Sx[1], fmaf( t1u.y, Sy[1], br));
                bi = fmaf(t1u.x, Sy[1], fmaf(-t1u.y, Sx[1], bi));
                br = fmaf(t2u.x, Sx[2], fmaf( t2u.y, Sy[2], br));
                bi = fmaf(t2u.x, Sy[2], fmaf(-t2u.y, Sx[2], bi));
                br = fmaf(t3u.x, Sx[3], fmaf( t3u.y, Sy[3], br));
                bi = fmaf(t3u.x, Sy[3], fmaf(-t3u.y, Sx[3], bi));
                zz[tid] = make_float2(br, bi);
            }
            __syncthreads();

            // Hermitian unpack: X1=(Z(w)+conj Z(-w))/2, X2=-i(Z(w)-conj Z(-w))/2
            const int co = conj_om(tid);
            if (tid <= co) {
                float2 A = zz[tid], B = zz[co];
                float x1r = 0.5f * (A.x + B.x);
                float x1i = 0.5f * (A.y - B.y);
                float x2r = 0.5f * (A.y + B.y);
                float x2i = 0.5f * (B.x - A.x);
                *reinterpret_cast<float4*>(outh + (size_t)tid * ostride + t0) =
                    make_float4(x1r, x1i, x2r, x2i);
            }
            __syncthreads();   // protect sr reuse next iteration
        }
    }

    grid_sync();

    // ======================= Phase 2: contraction ==========================
    if (blockIdx.x < S) {
        const int om = blockIdx.x;
        const int co = conj_om(om);
        if (om <= co) {
            float2* xh = (float2*) smraw;             //  4096 B  [b][i]
            float2* kh = (float2*)(smraw + 4096);     // 16640 B  [i][f] padded

            #pragma unroll
            for (int p = 0; p < 2; p++)
                xh[p * 256 + tid] = g_xhat[om * (NB * NI) + p * 256 + tid];
            #pragma unroll
            for (int p = 0; p < 8; p++) {
                int g = p * 256 + tid;
                int f = g >> 5, i = g & 31;
                kh[i * 65 + f] = g_khat[om * (NF * NI) + g];
            }
            __syncthreads();

            const int f  = tid & 63;
            const int b0 = tid >> 6;

            float accr[4] = {0.f, 0.f, 0.f, 0.f};
            float acci[4] = {0.f, 0.f, 0.f, 0.f};

            #pragma unroll 8
            for (int i = 0; i < NI; i++) {
                float2 kv = kh[i * 65 + f];
                #pragma unroll
                for (int r = 0; r < 4; r++) {
                    float2 xv = xh[(r * 4 + b0) * NI + i];
                    accr[r] = fmaf(xv.x, kv.x, fmaf(-xv.y, kv.y, accr[r]));
                    acci[r] = fmaf(xv.x, kv.y, fmaf( xv.y, kv.x, acci[r]));
                }
            }

            #pragma unroll
            for (int r = 0; r < 4; r++) {
                int b = r * 4 + b0;
                g_ohat[om * (NB * NF) + b * NF + f] = make_float2(accr[r], acci[r]);
                if (om != co)
                    g_ohat[co * (NB * NF) + b * NF + f] = make_float2(accr[r], -acci[r]);
            }
        }
    }

    grid_sync();

    // ======================= Phase 3: inverse FFT ==========================
    if (blockIdx.x < (NB * NF) / 2) {
        const int blk = blockIdx.x;
        const int b   = blk >> 5;
        const int f0  = (blk & 31) * 2;

        float2* sBt  = (float2*) smraw;               //  128 B
        float2* sinb = (float2*)(smraw + 128);        // 2048 B
        float2* st   = (float2*)(smraw + 2176);       // 2176 B

        if (tid < 16) sBt[tid] = make_float2(CW16[tid], SW16[tid]);
        {
            float4 z = *reinterpret_cast<const float4*>(
                g_ohat + (size_t)tid * (NB * NF) + b * NF + f0);
            sinb[tid] = make_float2(z.x - z.w, z.y + z.z);   // W = o0 + i*o1
        }
        __syncthreads();

        const float2 j1w = sBt[(4 * w) & 15];
        const float2 t1w = sBt[w], t2w = sBt[(2 * w) & 15], t3w = sBt[(3 * w) & 15];
        const float  ew  = 1.f - 2.f * (float)(w & 1);
        const float  jrw = j1w.x, jiw = j1w.y;

        const float2 j1u = sBt[(4 * u) & 15];
        const float2 t1u = sBt[u], t2u = sBt[(2 * u) & 15], t3u = sBt[(3 * u) & 15];
        const float  eu  = 1.f - 2.f * (float)(u & 1);
        const float  jru = j1u.x, jiu = j1u.y;

        // pass 1 over omega_v (inverse twiddles (c, +s))
        {
            float Sx[4], Sy[4];
            #pragma unroll
            for (int r = 0; r < 4; r++) {
                float2 z0 = sinb[u * 16 + r];
                float2 z1 = sinb[u * 16 + r + 4];
                float2 z2 = sinb[u * 16 + r + 8];
                float2 z3 = sinb[u * 16 + r + 12];
                float Px = fmaf(ew, z2.x, z0.x), Py = fmaf(ew, z2.y, z0.y);
                float Qx = fmaf(ew, z3.x, z1.x), Qy = fmaf(ew, z3.y, z1.y);
                Sx[r] = fmaf(jrw, Qx, fmaf(-jiw, Qy, Px));
                Sy[r] = fmaf(jrw, Qy, fmaf( jiw, Qx, Py));
            }
            float ar = Sx[0], ai = Sy[0];
            ar = fmaf(t1w.x, Sx[1], fmaf(-t1w.y, Sy[1], ar));
            ai = fmaf(t1w.x, Sy[1], fmaf( t1w.y, Sx[1], ai));
            ar = fmaf(t2w.x, Sx[2], fmaf(-t2w.y, Sy[2], ar));
            ai = fmaf(t2w.x, Sy[2], fmaf( t2w.y, Sx[2], ai));
            ar = fmaf(t3w.x, Sx[3], fmaf(-t3w.y, Sy[3], ar));
            ai = fmaf(t3w.x, Sy[3], fmaf( t3w.y, Sx[3], ai));
            st[u * 17 + w] = make_float2(ar, ai);
        }
        __syncthreads();

        // pass 2 over omega_u: Re -> f0, Im -> f0+1
        {
            float Sx[4], Sy[4];
            #pragma unroll
            for (int r = 0; r < 4; r++) {
                float2 z0 = st[(r     ) * 17 + w];
                float2 z1 = st[(r +  4) * 17 + w];
                float2 z2 = st[(r +  8) * 17 + w];
                float2 z3 = st[(r + 12) * 17 + w];
                float Px = fmaf(eu, z2.x, z0.x), Py = fmaf(eu, z2.y, z0.y);
                float Qx = fmaf(eu, z3.x, z1.x), Qy = fmaf(eu, z3.y, z1.y);
                Sx[r] = fmaf(jru, Qx, fmaf(-jiu, Qy, Px));
                Sy[r] = fmaf(jru, Qy, fmaf( jiu, Qx, Py));
            }
            float br = Sx[0], bi = Sy[0];
            br = fmaf(t1u.x, Sx[1], fmaf(-t1u.y, Sy[1], br));
            bi = fmaf(t1u.x, Sy[1], fmaf( t1u.y, Sx[1], bi));
            br = fmaf(t2u.x, Sx[2], fmaf(-t2u.y, Sy[2], br));
            bi = fmaf(t2u.x, Sy[2], fmaf( t2u.y, Sx[2], bi));
            br = fmaf(t3u.x, Sx[3], fmaf(-t3u.y, Sy[3], br));
            bi = fmaf(t3u.x, Sy[3], fmaf( t3u.y, Sx[3], bi));

            float* o = out + b * (NF * S) + f0 * S + tid;
            o[0] = br * (1.0f / 256.0f) + bias[f0];
            o[S] = bi * (1.0f / 256.0f) + bias[f0 + 1];
        }
    }
}

// ---------------------------------------------------------------------------
extern "C" void kernel_launch(void* const* d_in, const int* in_sizes, int n_in,
                              void* d_out, int out_size) {
    const float* x    = (const float*)d_in[0];   // (16, 32, 256)
    const float* kern = (const float*)d_in[1];   // (64, 32, 256)
    const float* bias = (const float*)d_in[2];   // (64,)
    // d_in[3] = product_table of the 2D translation group (deterministic);
    // exploited analytically via the convolution theorem.
    float* out = (float*)d_out;                  // (16, 64, 256)

    fused_kernel<<<GRID, 256>>>(x, kern, bias, out);
}